// round 5
// baseline (speedup 1.0000x reference)
#include <cuda_runtime.h>
#include <cuda_bf16.h>

#define BB 32
#define CC 64
#define TT 2048
#define KK 16
#define NST 6

#define TILE 64
#define HALO_L 15                    // causal window reach (K-1)
#define HALO_R 5                     // pooling reach for last strip item
#define ROWF (TILE + HALO_L + HALO_R)   // 84 filled
#define PITCH 85                     // odd -> conflict-free across c
#define WPAD 97
#define NTH 128
#define NTILES (TT / TILE)           // 32

__device__ float g_means[BB * CC];

__device__ __forceinline__ float sqrt_approx(float x) {
    float r; asm("sqrt.approx.f32 %0, %1;" : "=f"(r) : "f"(x)); return r;
}
__device__ __forceinline__ float rcp_approx(float x) {
    float r; asm("rcp.approx.f32 %0, %1;" : "=f"(r) : "f"(x)); return r;
}
__device__ __forceinline__ float apply_sign(float ev, float k) {
    return __uint_as_float(__float_as_uint(ev) | (__float_as_uint(k) & 0x80000000u));
}

// ---------------------------------------------------------------------------
// Kernel 1: per-(b,c) mean over T
// ---------------------------------------------------------------------------
__global__ void mean_kernel(const float* __restrict__ x) {
    int row = blockIdx.x;
    const float* xr = x + (size_t)row * TT;
    float s = 0.f;
    for (int t = threadIdx.x; t < TT; t += blockDim.x) s += xr[t];
    __shared__ float red[8];
    #pragma unroll
    for (int o = 16; o > 0; o >>= 1) s += __shfl_down_sync(0xffffffffu, s, o);
    if ((threadIdx.x & 31) == 0) red[threadIdx.x >> 5] = s;
    __syncthreads();
    if (threadIdx.x < 8) {
        s = red[threadIdx.x];
        #pragma unroll
        for (int o = 4; o > 0; o >>= 1) s += __shfl_down_sync(0xffu, s, o);
        if (threadIdx.x == 0) g_means[row] = s * (1.0f / TT);
    }
}

// ---------------------------------------------------------------------------
// One item (fully independent of its neighbors -> cross-item ILP).
// v[0..20] = x[t-15 .. t+5] for the strip; item m uses v[m..m+15] (gather)
// and v[13+m..17+m] (pool).
// ---------------------------------------------------------------------------
template <bool EDGE>
__device__ __forceinline__ float do_item(
    const float* __restrict__ v, int m,
    const float* __restrict__ w,    // 80 regs: per k {w0, w2, w3, w4, w5}
    const float* __restrict__ bs2,  // bias + w1*g_mean
    int tg)                         // global t of this item
{
    const float a0 = v[13 + m], a1 = v[14 + m], a2 = v[15 + m],
                a3 = v[16 + m], a4 = v[17 + m];

    // pool sums, tree form (no cross-item carry)
    const float s  = ((a0 + a1) + (a2 + a3)) + a4;
    const float s2 = fmaf(a0, a0, fmaf(a1, a1, 0.f))
                   + fmaf(a2, a2, fmaf(a3, a3, a4 * a4));

    const float xv   = a2;
    const float avg  = s * 0.2f;
    const float sd   = sqrt_approx(fmaxf(fmaf(-avg, avg, s2 * 0.2f), 1e-6f));
    const float d    = xv - avg;
    const float tm   = d * d * d;

    float mx, mn;
    if (EDGE) {
        mx = -3.402823466e38f; mn = 3.402823466e38f;
        #pragma unroll
        for (int j = -2; j <= 2; j++) {
            int g = tg + j;
            if (g >= 0 && g < TT) {
                float t = v[15 + m + j];
                mx = fmaxf(mx, t); mn = fminf(mn, t);
            }
        }
    } else {
        mx = fmaxf(fmaxf(fmaxf(a0, a1), fmaxf(a2, a3)), a4);
        mn = fminf(fminf(fminf(a0, a1), fminf(a2, a3)), a4);
    }

    // grouped 1x1 conv (g_mean term pre-folded into bs2)
    float kern[KK];
    #pragma unroll
    for (int k = 0; k < KK; k++) {
        const float* wk = w + k * 5;
        float a = bs2[k];
        a = fmaf(wk[0], xv, a);
        a = fmaf(wk[1], sd, a);
        a = fmaf(wk[2], tm, a);
        a = fmaf(wk[3], mx, a);
        a = fmaf(wk[4], mn, a);
        kern[k] = a;
    }

    // softmax over |kern|, sign folded; all exps independent -> MUFU pipelines
    float ev[KK];
    #pragma unroll
    for (int k = 0; k < KK; k++) ev[k] = __expf(fabsf(kern[k]));

    // products (independent FMULs); reuse kern[] as product array
    #pragma unroll
    for (int k = 0; k < KK; k++) kern[k] = v[m + k] * apply_sign(ev[k], kern[k]);

    // tree reductions: depth 4 instead of 16-deep serial chains
    #pragma unroll
    for (int st = 8; st >= 1; st >>= 1) {
        #pragma unroll
        for (int k = 0; k < st; k++) {
            ev[k]   += ev[k + st];
            kern[k] += kern[k + st];
        }
    }
    return kern[0] * rcp_approx(ev[0]);
}

// ---------------------------------------------------------------------------
// Kernel 2: CTA = 128 threads (c = tid&63, g = tid>>6), tile of 64 t's.
// ---------------------------------------------------------------------------
extern __shared__ float smem[];

__global__ __launch_bounds__(NTH, 3)
void ddst_main_kernel(const float* __restrict__ x,
                      const float* __restrict__ W,
                      const float* __restrict__ bias,
                      float* __restrict__ out) {
    float* xs = smem;                   // [C][PITCH]
    float* ws = smem + CC * PITCH;      // [C][WPAD]

    const int b    = blockIdx.x / NTILES;
    const int tile = blockIdx.x % NTILES;
    const int t0   = tile * TILE;
    const int tid  = threadIdx.x;
    const int warp = tid >> 5;
    const int lane = tid & 31;

    const float* xb = x + (size_t)b * CC * TT;

    for (int cr = warp; cr < CC; cr += NTH / 32) {
        const float* src = xb + (size_t)cr * TT;
        float* dst = xs + cr * PITCH;
        for (int j = lane; j < ROWF; j += 32) {
            int gt = t0 - HALO_L + j;
            dst[j] = (gt >= 0 && gt < TT) ? src[gt] : 0.f;
        }
    }
    for (int cr = warp; cr < CC; cr += NTH / 32) {
        const float* src = W + cr * (KK * NST);
        float* dst = ws + cr * WPAD;
        for (int j = lane; j < KK * NST; j += 32) dst[j] = src[j];
    }
    __syncthreads();

    const int c = tid & (CC - 1);
    const int g = tid >> 6;          // 0 or 1

    float w[KK * 5];
    #pragma unroll
    for (int k = 0; k < KK; k++) {
        const float* sw = ws + c * WPAD + k * NST;
        w[k * 5 + 0] = sw[0];
        w[k * 5 + 1] = sw[2];
        w[k * 5 + 2] = sw[3];
        w[k * 5 + 3] = sw[4];
        w[k * 5 + 4] = sw[5];
    }
    const float gm = g_means[b * CC + c];
    float bs2[KK];
    #pragma unroll
    for (int k = 0; k < KK; k++)
        bs2[k] = fmaf(ws[c * WPAD + k * NST + 1], gm, __ldg(&bias[c * KK + k]));

    const float* xc = xs + c * PITCH + HALO_L;
    float* outb = out + ((size_t)b * TT + t0) * CC + c;

    const bool edge = (tile == 0) || (tile == NTILES - 1);

    // 8 strips of 4 items; within a strip items are independent
    if (edge) {
        for (int i = 0; i < 8; i++) {
            int tl = g * 4 + i * 8;
            float v[21];
            #pragma unroll
            for (int j = 0; j < 21; j++) v[j] = xc[tl - 15 + j];
            #pragma unroll
            for (int m = 0; m < 4; m++)
                outb[(tl + m) * CC] = do_item<true>(v, m, w, bs2, t0 + tl + m);
        }
    } else {
        for (int i = 0; i < 8; i++) {
            int tl = g * 4 + i * 8;
            float v[21];
            #pragma unroll
            for (int j = 0; j < 21; j++) v[j] = xc[tl - 15 + j];
            #pragma unroll
            for (int m = 0; m < 4; m++)
                outb[(tl + m) * CC] = do_item<false>(v, m, w, bs2, t0 + tl + m);
        }
    }
}

// ---------------------------------------------------------------------------
extern "C" void kernel_launch(void* const* d_in, const int* in_sizes, int n_in,
                              void* d_out, int out_size) {
    const float* x    = (const float*)d_in[0];   // [B, C, T]
    const float* W    = (const float*)d_in[1];   // [C, K, 6]
    const float* bias = (const float*)d_in[2];   // [C, K]
    float* out = (float*)d_out;                  // [B, T, C]

    (void)in_sizes; (void)n_in; (void)out_size;

    mean_kernel<<<BB * CC, 256>>>(x);

    const int smem_bytes = (CC * PITCH + CC * WPAD) * (int)sizeof(float);
    cudaFuncSetAttribute(ddst_main_kernel,
                         cudaFuncAttributeMaxDynamicSharedMemorySize, smem_bytes);
    ddst_main_kernel<<<BB * NTILES, NTH, smem_bytes>>>(x, W, bias, out);
}

// round 6
// speedup vs baseline: 1.2632x; 1.2632x over previous
#include <cuda_runtime.h>
#include <cuda_bf16.h>

#define BB 32
#define CC 64
#define TT 2048
#define KK 16
#define NST 6

#define TILE 64
#define HALO_L 15
#define HALO_R 5
#define ROWF (TILE + HALO_L + HALO_R)   // 84
#define PITCH 85                         // odd -> conflict-free across c
#define NTH 128
#define NTILES (TT / TILE)               // 32
#define LOG2E 1.4426950408889634f

__device__ float g_means[BB * CC];

__device__ __forceinline__ float sqrt_approx(float x) {
    float r; asm("sqrt.approx.f32 %0, %1;" : "=f"(r) : "f"(x)); return r;
}
__device__ __forceinline__ float rcp_approx(float x) {
    float r; asm("rcp.approx.f32 %0, %1;" : "=f"(r) : "f"(x)); return r;
}
__device__ __forceinline__ float ex2_approx(float x) {
    float r; asm("ex2.approx.f32 %0, %1;" : "=f"(r) : "f"(x)); return r;
}
__device__ __forceinline__ float apply_sign(float ev, float k) {
    return __uint_as_float(__float_as_uint(ev) | (__float_as_uint(k) & 0x80000000u));
}

// ---------------------------------------------------------------------------
// Kernel 1: per-(b,c) mean over T
// ---------------------------------------------------------------------------
__global__ void mean_kernel(const float* __restrict__ x) {
    int row = blockIdx.x;
    const float* xr = x + (size_t)row * TT;
    float s = 0.f;
    for (int t = threadIdx.x; t < TT; t += blockDim.x) s += xr[t];
    __shared__ float red[8];
    #pragma unroll
    for (int o = 16; o > 0; o >>= 1) s += __shfl_down_sync(0xffffffffu, s, o);
    if ((threadIdx.x & 31) == 0) red[threadIdx.x >> 5] = s;
    __syncthreads();
    if (threadIdx.x < 8) {
        s = red[threadIdx.x];
        #pragma unroll
        for (int o = 4; o > 0; o >>= 1) s += __shfl_down_sync(0xffu, s, o);
        if (threadIdx.x == 0) g_means[row] = s * (1.0f / TT);
    }
}

// ---------------------------------------------------------------------------
// Strip of 4 items, HALF the K taps per thread (k in [k0, k0+8)).
// Thread pair (lanes differing in bit 0) combines partials via shfl_xor.
// ---------------------------------------------------------------------------
template <bool EDGE>
__device__ __forceinline__ void do_strip(
    const float* __restrict__ xc,   // xc[tl] == x[b,c,t0+tl] (smem, zero-padded)
    int tl, int k0,                 // k0 = half * 8
    const float* __restrict__ w,    // 40 regs: per k {w0,w2,w3,w4,w5} * LOG2E
    const float* __restrict__ bs2,  // 8 regs: (bias + w1*gm) * LOG2E
    float* __restrict__ outp,       // &out[b, t0+tl, c]; stride CC
    int tg0, bool store_en)
{
    // gather taps for items m=0..3, taps k=0..7: x[t + (k0+k) - 15] = vg[m+k]
    float vg[11];
    const float* gb = xc + tl + k0 - 15;
    #pragma unroll
    for (int i = 0; i < 11; i++) vg[i] = gb[i];
    // pool window values: vp[i] = x[t0+tl-2+i]
    float vp[8];
    #pragma unroll
    for (int i = 0; i < 8; i++) vp[i] = xc[tl - 2 + i];

    #pragma unroll
    for (int m = 0; m < 4; m++) {
        const float a0 = vp[m], a1 = vp[m+1], a2 = vp[m+2],
                    a3 = vp[m+3], a4 = vp[m+4];
        const float s  = ((a0 + a1) + (a2 + a3)) + a4;
        const float s2 = fmaf(a0, a0, a1 * a1)
                       + fmaf(a2, a2, fmaf(a3, a3, a4 * a4));
        const float xv  = a2;
        const float avg = s * 0.2f;
        const float sd  = sqrt_approx(fmaxf(fmaf(-avg, avg, s2 * 0.2f), 1e-6f));
        const float d   = xv - avg;
        const float tm  = d * d * d;

        float mx, mn;
        if (EDGE) {
            mx = -3.402823466e38f; mn = 3.402823466e38f;
            #pragma unroll
            for (int j = -2; j <= 2; j++) {
                int g = tg0 + m + j;
                if (g >= 0 && g < TT) {
                    float t = vp[m + 2 + j];
                    mx = fmaxf(mx, t); mn = fminf(mn, t);
                }
            }
        } else {
            mx = fmaxf(fmaxf(fmaxf(a0, a1), fmaxf(a2, a3)), a4);
            mn = fminf(fminf(fminf(a0, a1), fminf(a2, a3)), a4);
        }

        // 8 of 16 conv taps (weights pre-scaled by LOG2E)
        float kern[8], ev[8];
        #pragma unroll
        for (int k = 0; k < 8; k++) {
            const float* wk = w + k * 5;
            float a = bs2[k];
            a = fmaf(wk[0], xv, a);
            a = fmaf(wk[1], sd, a);
            a = fmaf(wk[2], tm, a);
            a = fmaf(wk[3], mx, a);
            a = fmaf(wk[4], mn, a);
            kern[k] = a;
        }
        #pragma unroll
        for (int k = 0; k < 8; k++) ev[k] = ex2_approx(fabsf(kern[k]));
        #pragma unroll
        for (int k = 0; k < 8; k++)
            kern[k] = vg[m + k] * apply_sign(ev[k], kern[k]);

        // local trees (depth 3)
        #pragma unroll
        for (int st = 4; st >= 1; st >>= 1) {
            #pragma unroll
            for (int k = 0; k < st; k++) {
                ev[k]   += ev[k + st];
                kern[k] += kern[k + st];
            }
        }
        // cross-half combine
        float sum = ev[0]   + __shfl_xor_sync(0xffffffffu, ev[0],   1);
        float acc = kern[0] + __shfl_xor_sync(0xffffffffu, kern[0], 1);
        if (store_en) outp[m * CC] = acc * rcp_approx(sum);
    }
}

// ---------------------------------------------------------------------------
// Kernel 2: CTA = 128 threads = 64 channels x 2 K-halves, tile of 64 t's.
// Weights per thread: 40 regs (half the taps) -> ~4-5 CTAs/SM.
// ---------------------------------------------------------------------------
extern __shared__ float smem[];

__global__ __launch_bounds__(NTH, 4)
void ddst_main_kernel(const float* __restrict__ x,
                      const float* __restrict__ W,
                      const float* __restrict__ bias,
                      float* __restrict__ out) {
    float* xs = smem;                   // [C][PITCH]

    const int b    = blockIdx.x / NTILES;
    const int tile = blockIdx.x % NTILES;
    const int t0   = tile * TILE;
    const int tid  = threadIdx.x;
    const int warp = tid >> 5;
    const int lane = tid & 31;

    const float* xb = x + (size_t)b * CC * TT;

    // x tile + halo (zeros outside [0,T))
    for (int cr = warp; cr < CC; cr += NTH / 32) {
        const float* src = xb + (size_t)cr * TT;
        float* dst = xs + cr * PITCH;
        for (int j = lane; j < ROWF; j += 32) {
            int gt = t0 - HALO_L + j;
            dst[j] = (gt >= 0 && gt < TT) ? src[gt] : 0.f;
        }
    }
    __syncthreads();

    const int c    = tid >> 1;         // 0..63
    const int half = tid & 1;          // shfl pair = adjacent lanes
    const int k0   = half * 8;

    // per-thread weights straight from gmem (coalesced 48-float segments,
    // L2-resident across CTAs); fold g_mean into bias, scale all by LOG2E
    const float gm = g_means[b * CC + c];
    const float* Wp = W + c * (KK * NST) + k0 * NST;
    float w[40], bs2[8];
    #pragma unroll
    for (int k = 0; k < 8; k++) {
        const float* wk6 = Wp + k * NST;
        float w0 = __ldg(wk6 + 0), w1 = __ldg(wk6 + 1), w2 = __ldg(wk6 + 2);
        float w3 = __ldg(wk6 + 3), w4 = __ldg(wk6 + 4), w5 = __ldg(wk6 + 5);
        w[k*5+0] = w0 * LOG2E;
        w[k*5+1] = w2 * LOG2E;
        w[k*5+2] = w3 * LOG2E;
        w[k*5+3] = w4 * LOG2E;
        w[k*5+4] = w5 * LOG2E;
        bs2[k] = fmaf(w1, gm, __ldg(&bias[c * KK + k0 + k])) * LOG2E;
    }

    const float* xc = xs + c * PITCH + HALO_L;
    float* outb = out + ((size_t)b * TT + t0) * CC + c;
    const bool store_en = (half == 0);

    if (tile == 0 || tile == NTILES - 1) {
        #pragma unroll 2
        for (int i = 0; i < 16; i++) {
            int tl = i * 4;
            do_strip<true>(xc, tl, k0, w, bs2, outb + tl * CC, t0 + tl, store_en);
        }
    } else {
        #pragma unroll 2
        for (int i = 0; i < 16; i++) {
            int tl = i * 4;
            do_strip<false>(xc, tl, k0, w, bs2, outb + tl * CC, t0 + tl, store_en);
        }
    }
}

// ---------------------------------------------------------------------------
extern "C" void kernel_launch(void* const* d_in, const int* in_sizes, int n_in,
                              void* d_out, int out_size) {
    const float* x    = (const float*)d_in[0];   // [B, C, T]
    const float* W    = (const float*)d_in[1];   // [C, K, 6]
    const float* bias = (const float*)d_in[2];   // [C, K]
    float* out = (float*)d_out;                  // [B, T, C]

    (void)in_sizes; (void)n_in; (void)out_size;

    mean_kernel<<<BB * CC, 256>>>(x);

    const int smem_bytes = (CC * PITCH) * (int)sizeof(float);
    cudaFuncSetAttribute(ddst_main_kernel,
                         cudaFuncAttributeMaxDynamicSharedMemorySize, smem_bytes);
    ddst_main_kernel<<<BB * NTILES, NTH, smem_bytes>>>(x, W, bias, out);
}

// round 7
// speedup vs baseline: 1.3727x; 1.0867x over previous
#include <cuda_runtime.h>
#include <cuda_bf16.h>

#define BB 32
#define CC 64
#define TT 2048
#define KK 16
#define NST 6

#define TILE 64
#define HALO_L 15
#define HALO_R 5
#define ROWF (TILE + HALO_L + HALO_R)   // 84
#define PITCH 85                         // odd -> conflict-free
#define CH 32                            // channels per CTA
#define NTH 128                          // 32 channels x 4 K-quarters
#define NTILES (TT / TILE)               // 32
#define LOG2E 1.4426950408889634f

__device__ float g_means[BB * CC];

__device__ __forceinline__ float sqrt_approx(float x) {
    float r; asm("sqrt.approx.f32 %0, %1;" : "=f"(r) : "f"(x)); return r;
}
__device__ __forceinline__ float rcp_approx(float x) {
    float r; asm("rcp.approx.f32 %0, %1;" : "=f"(r) : "f"(x)); return r;
}
__device__ __forceinline__ float ex2_approx(float x) {
    float r; asm("ex2.approx.f32 %0, %1;" : "=f"(r) : "f"(x)); return r;
}
__device__ __forceinline__ float apply_sign(float ev, float k) {
    return __uint_as_float(__float_as_uint(ev) | (__float_as_uint(k) & 0x80000000u));
}

// ---------------------------------------------------------------------------
// Kernel 1: per-(b,c) mean over T
// ---------------------------------------------------------------------------
__global__ void mean_kernel(const float* __restrict__ x) {
    int row = blockIdx.x;
    const float* xr = x + (size_t)row * TT;
    float s = 0.f;
    for (int t = threadIdx.x; t < TT; t += blockDim.x) s += xr[t];
    __shared__ float red[8];
    #pragma unroll
    for (int o = 16; o > 0; o >>= 1) s += __shfl_down_sync(0xffffffffu, s, o);
    if ((threadIdx.x & 31) == 0) red[threadIdx.x >> 5] = s;
    __syncthreads();
    if (threadIdx.x < 8) {
        s = red[threadIdx.x];
        #pragma unroll
        for (int o = 4; o > 0; o >>= 1) s += __shfl_down_sync(0xffu, s, o);
        if (threadIdx.x == 0) g_means[row] = s * (1.0f / TT);
    }
}

// ---------------------------------------------------------------------------
// Strip of 4 items, QUARTER of the K taps per thread (k in [k0, k0+4)).
// 4 adjacent lanes (same c) combine partials via 2-level shfl_xor butterfly.
// ---------------------------------------------------------------------------
template <bool EDGE>
__device__ __forceinline__ void do_strip(
    const float* __restrict__ xc,   // xc[tl] == x[b,c,t0+tl] (smem, zero-pad)
    int tl, int k0,                 // k0 = quarter * 4
    const float* __restrict__ w,    // 20 regs: per k {w0,w2,w3,w4,w5} * LOG2E
    const float* __restrict__ bs2,  // 4 regs
    float* __restrict__ outp,       // &out[b, t0+tl, c]; stride CC
    int tg0, bool store_en)
{
    // gather taps: item m, tap k -> x[t + k0 + k - 15] = vg[m + k], i in [0,6]
    float vg[7];
    const float* gb = xc + tl + k0 - 15;
    #pragma unroll
    for (int i = 0; i < 7; i++) vg[i] = gb[i];
    // pool window: vp[i] = x[t0+tl-2+i]
    float vp[8];
    #pragma unroll
    for (int i = 0; i < 8; i++) vp[i] = xc[tl - 2 + i];

    #pragma unroll
    for (int m = 0; m < 4; m++) {
        const float a0 = vp[m], a1 = vp[m+1], a2 = vp[m+2],
                    a3 = vp[m+3], a4 = vp[m+4];
        const float s  = ((a0 + a1) + (a2 + a3)) + a4;
        const float s2 = fmaf(a0, a0, a1 * a1)
                       + fmaf(a2, a2, fmaf(a3, a3, a4 * a4));
        const float xv  = a2;
        const float avg = s * 0.2f;
        const float sd  = sqrt_approx(fmaxf(fmaf(-avg, avg, s2 * 0.2f), 1e-6f));
        const float d   = xv - avg;
        const float tm  = d * d * d;

        float mx, mn;
        if (EDGE) {
            mx = -3.402823466e38f; mn = 3.402823466e38f;
            #pragma unroll
            for (int j = -2; j <= 2; j++) {
                int g = tg0 + m + j;
                if (g >= 0 && g < TT) {
                    float t = vp[m + 2 + j];
                    mx = fmaxf(mx, t); mn = fminf(mn, t);
                }
            }
        } else {
            mx = fmaxf(fmaxf(fmaxf(a0, a1), fmaxf(a2, a3)), a4);
            mn = fminf(fminf(fminf(a0, a1), fminf(a2, a3)), a4);
        }

        // 4 of 16 conv taps (weights pre-scaled by LOG2E)
        float kern[4], ev[4];
        #pragma unroll
        for (int k = 0; k < 4; k++) {
            const float* wk = w + k * 5;
            float a = bs2[k];
            a = fmaf(wk[0], xv, a);
            a = fmaf(wk[1], sd, a);
            a = fmaf(wk[2], tm, a);
            a = fmaf(wk[3], mx, a);
            a = fmaf(wk[4], mn, a);
            kern[k] = a;
        }
        #pragma unroll
        for (int k = 0; k < 4; k++) ev[k] = ex2_approx(fabsf(kern[k]));
        #pragma unroll
        for (int k = 0; k < 4; k++)
            kern[k] = vg[m + k] * apply_sign(ev[k], kern[k]);

        float sum = (ev[0] + ev[1]) + (ev[2] + ev[3]);
        float acc = (kern[0] + kern[1]) + (kern[2] + kern[3]);
        // butterfly across the 4-lane group
        sum += __shfl_xor_sync(0xffffffffu, sum, 1);
        acc += __shfl_xor_sync(0xffffffffu, acc, 1);
        sum += __shfl_xor_sync(0xffffffffu, sum, 2);
        acc += __shfl_xor_sync(0xffffffffu, acc, 2);
        if (store_en) outp[m * CC] = acc * rcp_approx(sum);
    }
}

// ---------------------------------------------------------------------------
// Kernel 2: CTA = 128 threads = 32 channels x 4 K-quarters, tile of 64 t's.
// ---------------------------------------------------------------------------
extern __shared__ float smem[];

__global__ __launch_bounds__(NTH, 7)
void ddst_main_kernel(const float* __restrict__ x,
                      const float* __restrict__ W,
                      const float* __restrict__ bias,
                      float* __restrict__ out) {
    float* xs = smem;                   // [CH][PITCH]

    const int bt   = blockIdx.x >> 1;          // b * NTILES + tile
    const int ch0  = (blockIdx.x & 1) * CH;    // channel group base
    const int b    = bt / NTILES;
    const int tile = bt % NTILES;
    const int t0   = tile * TILE;
    const int tid  = threadIdx.x;
    const int warp = tid >> 5;
    const int lane = tid & 31;

    const float* xb = x + ((size_t)b * CC + ch0) * TT;

    // x tile + halo (zeros outside [0,T)): warp per channel row, stride 4
    for (int cr = warp; cr < CH; cr += NTH / 32) {
        const float* src = xb + (size_t)cr * TT;
        float* dst = xs + cr * PITCH;
        for (int j = lane; j < ROWF; j += 32) {
            int gt = t0 - HALO_L + j;
            dst[j] = (gt >= 0 && gt < TT) ? src[gt] : 0.f;
        }
    }
    __syncthreads();

    const int cl = tid >> 2;          // 0..31 local channel
    const int q  = tid & 3;           // K-quarter; 4 adjacent lanes share c
    const int k0 = q * 4;
    const int c  = ch0 + cl;

    // per-thread weights from gmem (L2-resident), g_mean folded, LOG2E scaled
    const float gm = g_means[b * CC + c];
    const float* Wp = W + c * (KK * NST) + k0 * NST;
    float w[20], bs2[4];
    #pragma unroll
    for (int k = 0; k < 4; k++) {
        const float* wk6 = Wp + k * NST;
        float w0 = __ldg(wk6 + 0), w1 = __ldg(wk6 + 1), w2 = __ldg(wk6 + 2);
        float w3 = __ldg(wk6 + 3), w4 = __ldg(wk6 + 4), w5 = __ldg(wk6 + 5);
        w[k*5+0] = w0 * LOG2E;
        w[k*5+1] = w2 * LOG2E;
        w[k*5+2] = w3 * LOG2E;
        w[k*5+3] = w4 * LOG2E;
        w[k*5+4] = w5 * LOG2E;
        bs2[k] = fmaf(w1, gm, __ldg(&bias[c * KK + k0 + k])) * LOG2E;
    }

    const float* xc = xs + cl * PITCH + HALO_L;
    float* outb = out + ((size_t)b * TT + t0) * CC + c;
    const bool store_en = (q == 0);

    if (tile == 0 || tile == NTILES - 1) {
        #pragma unroll 2
        for (int i = 0; i < 16; i++) {
            int tl = i * 4;
            do_strip<true>(xc, tl, k0, w, bs2, outb + tl * CC, t0 + tl, store_en);
        }
    } else {
        #pragma unroll 2
        for (int i = 0; i < 16; i++) {
            int tl = i * 4;
            do_strip<false>(xc, tl, k0, w, bs2, outb + tl * CC, t0 + tl, store_en);
        }
    }
}

// ---------------------------------------------------------------------------
extern "C" void kernel_launch(void* const* d_in, const int* in_sizes, int n_in,
                              void* d_out, int out_size) {
    const float* x    = (const float*)d_in[0];   // [B, C, T]
    const float* W    = (const float*)d_in[1];   // [C, K, 6]
    const float* bias = (const float*)d_in[2];   // [C, K]
    float* out = (float*)d_out;                  // [B, T, C]

    (void)in_sizes; (void)n_in; (void)out_size;

    mean_kernel<<<BB * CC, 256>>>(x);

    const int smem_bytes = (CH * PITCH) * (int)sizeof(float);
    cudaFuncSetAttribute(ddst_main_kernel,
                         cudaFuncAttributeMaxDynamicSharedMemorySize, smem_bytes);
    ddst_main_kernel<<<BB * NTILES * 2, NTH, smem_bytes>>>(x, W, bias, out);
}

// round 8
// speedup vs baseline: 1.4993x; 1.0922x over previous
#include <cuda_runtime.h>
#include <cuda_bf16.h>

#define BB 32
#define CC 64
#define TT 2048
#define KK 16
#define NST 6

#define TILE 64
#define HALO_L 15
#define HALO_R 5
#define ROWF (TILE + HALO_L + HALO_R)   // 84
#define PITCH 85                         // odd -> conflict-free
#define CH 32                            // channels per CTA
#define NTH 128                          // 32 channels x 4 K-quarters
#define NTILES (TT / TILE)               // 32
#define LOG2E 1.4426950408889634f

__device__ float g_means[BB * CC];

__device__ __forceinline__ float sqrt_approx(float x) {
    float r; asm("sqrt.approx.f32 %0, %1;" : "=f"(r) : "f"(x)); return r;
}
__device__ __forceinline__ float rcp_approx(float x) {
    float r; asm("rcp.approx.f32 %0, %1;" : "=f"(r) : "f"(x)); return r;
}
__device__ __forceinline__ float ex2_approx(float x) {
    float r; asm("ex2.approx.f32 %0, %1;" : "=f"(r) : "f"(x)); return r;
}
__device__ __forceinline__ float apply_sign(float ev, float k) {
    return __uint_as_float(__float_as_uint(ev) | (__float_as_uint(k) & 0x80000000u));
}

// ---------------------------------------------------------------------------
// Kernel 1: per-(b,c) mean over T
// ---------------------------------------------------------------------------
__global__ void mean_kernel(const float* __restrict__ x) {
    int row = blockIdx.x;
    const float* xr = x + (size_t)row * TT;
    float s = 0.f;
    for (int t = threadIdx.x; t < TT; t += blockDim.x) s += xr[t];
    __shared__ float red[8];
    #pragma unroll
    for (int o = 16; o > 0; o >>= 1) s += __shfl_down_sync(0xffffffffu, s, o);
    if ((threadIdx.x & 31) == 0) red[threadIdx.x >> 5] = s;
    __syncthreads();
    if (threadIdx.x < 8) {
        s = red[threadIdx.x];
        #pragma unroll
        for (int o = 4; o > 0; o >>= 1) s += __shfl_down_sync(0xffu, s, o);
        if (threadIdx.x == 0) g_means[row] = s * (1.0f / TT);
    }
}

// ---------------------------------------------------------------------------
// Strip of 4 items. STATS TRANSPOSE: lane q of the 4-lane group computes
// stats for item m=q only (no duplication); width-4 shfl broadcasts them.
// Each lane still owns its K-quarter (k in [k0, k0+4)) for the conv/gather.
// ---------------------------------------------------------------------------
template <bool EDGE>
__device__ __forceinline__ void do_strip(
    const float* __restrict__ xc,   // xc[tl] == x[b,c,t0+tl] (smem, zero-pad)
    int tl, int q,                  // q = lane's quarter AND its stats item
    const float* __restrict__ w,    // 20 regs: per k {w0,w2,w3,w4,w5} * LOG2E
    const float* __restrict__ bs2,  // 4 regs
    float* __restrict__ outp,       // &out[b, t0+tl, c]; stride CC
    int tg0, bool store_en)
{
    const int k0 = q * 4;

    // gather taps for this lane's quarter: item m, tap k -> vg[m + k]
    float vg[7];
    const float* gb = xc + tl + k0 - 15;
    #pragma unroll
    for (int i = 0; i < 7; i++) vg[i] = gb[i];

    // ---- own-item stats (item m = q, t = t0 + tl + q) ----
    const int ts = tl + q;
    const float a0 = xc[ts - 2], a1 = xc[ts - 1], a2 = xc[ts],
                a3 = xc[ts + 1], a4 = xc[ts + 2];
    const float s  = ((a0 + a1) + (a2 + a3)) + a4;
    const float s2 = fmaf(a0, a0, a1 * a1)
                   + fmaf(a2, a2, fmaf(a3, a3, a4 * a4));
    const float xv  = a2;
    const float avg = s * 0.2f;
    const float sd  = sqrt_approx(fmaxf(fmaf(-avg, avg, s2 * 0.2f), 1e-6f));
    const float dd  = xv - avg;
    const float tm  = dd * dd * dd;

    float mx, mn;
    if (EDGE) {
        mx = -3.402823466e38f; mn = 3.402823466e38f;
        const int tg = tg0 + q;
        #pragma unroll
        for (int j = -2; j <= 2; j++) {
            int g = tg + j;
            if (g >= 0 && g < TT) {
                float t = xc[ts + j];
                mx = fmaxf(mx, t); mn = fminf(mn, t);
            }
        }
    } else {
        mx = fmaxf(fmaxf(fmaxf(a0, a1), fmaxf(a2, a3)), a4);
        mn = fminf(fminf(fminf(a0, a1), fminf(a2, a3)), a4);
    }

    // ---- 4 items: broadcast stats from owning lane, conv + softmax-gather --
    #pragma unroll
    for (int m = 0; m < 4; m++) {
        const float xv_m = __shfl_sync(0xffffffffu, xv, m, 4);
        const float sd_m = __shfl_sync(0xffffffffu, sd, m, 4);
        const float tm_m = __shfl_sync(0xffffffffu, tm, m, 4);
        const float mx_m = __shfl_sync(0xffffffffu, mx, m, 4);
        const float mn_m = __shfl_sync(0xffffffffu, mn, m, 4);

        float kern[4], ev[4];
        #pragma unroll
        for (int k = 0; k < 4; k++) {
            const float* wk = w + k * 5;
            float a = bs2[k];
            a = fmaf(wk[0], xv_m, a);
            a = fmaf(wk[1], sd_m, a);
            a = fmaf(wk[2], tm_m, a);
            a = fmaf(wk[3], mx_m, a);
            a = fmaf(wk[4], mn_m, a);
            kern[k] = a;
        }
        #pragma unroll
        for (int k = 0; k < 4; k++) ev[k] = ex2_approx(fabsf(kern[k]));
        #pragma unroll
        for (int k = 0; k < 4; k++)
            kern[k] = vg[m + k] * apply_sign(ev[k], kern[k]);

        float sum = (ev[0] + ev[1]) + (ev[2] + ev[3]);
        float acc = (kern[0] + kern[1]) + (kern[2] + kern[3]);
        sum += __shfl_xor_sync(0xffffffffu, sum, 1);
        acc += __shfl_xor_sync(0xffffffffu, acc, 1);
        sum += __shfl_xor_sync(0xffffffffu, sum, 2);
        acc += __shfl_xor_sync(0xffffffffu, acc, 2);
        if (store_en) outp[m * CC] = acc * rcp_approx(sum);
    }
}

// ---------------------------------------------------------------------------
// Kernel 2: CTA = 128 threads = 32 channels x 4 K-quarters, tile of 64 t's.
// ---------------------------------------------------------------------------
extern __shared__ float smem[];

__global__ __launch_bounds__(NTH, 7)
void ddst_main_kernel(const float* __restrict__ x,
                      const float* __restrict__ W,
                      const float* __restrict__ bias,
                      float* __restrict__ out) {
    float* xs = smem;                   // [CH][PITCH]

    const int bt   = blockIdx.x >> 1;          // b * NTILES + tile
    const int ch0  = (blockIdx.x & 1) * CH;    // channel group base
    const int b    = bt / NTILES;
    const int tile = bt % NTILES;
    const int t0   = tile * TILE;
    const int tid  = threadIdx.x;
    const int warp = tid >> 5;
    const int lane = tid & 31;

    const float* xb = x + ((size_t)b * CC + ch0) * TT;

    for (int cr = warp; cr < CH; cr += NTH / 32) {
        const float* src = xb + (size_t)cr * TT;
        float* dst = xs + cr * PITCH;
        for (int j = lane; j < ROWF; j += 32) {
            int gt = t0 - HALO_L + j;
            dst[j] = (gt >= 0 && gt < TT) ? src[gt] : 0.f;
        }
    }
    __syncthreads();

    const int cl = tid >> 2;          // 0..31 local channel
    const int q  = tid & 3;           // quarter = stats-item index
    const int k0 = q * 4;
    const int c  = ch0 + cl;

    const float gm = g_means[b * CC + c];
    const float* Wp = W + c * (KK * NST) + k0 * NST;
    float w[20], bs2[4];
    #pragma unroll
    for (int k = 0; k < 4; k++) {
        const float* wk6 = Wp + k * NST;
        float w0 = __ldg(wk6 + 0), w1 = __ldg(wk6 + 1), w2 = __ldg(wk6 + 2);
        float w3 = __ldg(wk6 + 3), w4 = __ldg(wk6 + 4), w5 = __ldg(wk6 + 5);
        w[k*5+0] = w0 * LOG2E;
        w[k*5+1] = w2 * LOG2E;
        w[k*5+2] = w3 * LOG2E;
        w[k*5+3] = w4 * LOG2E;
        w[k*5+4] = w5 * LOG2E;
        bs2[k] = fmaf(w1, gm, __ldg(&bias[c * KK + k0 + k])) * LOG2E;
    }

    const float* xc = xs + cl * PITCH + HALO_L;
    float* outb = out + ((size_t)b * TT + t0) * CC + c;
    const bool store_en = (q == 0);

    if (tile == 0 || tile == NTILES - 1) {
        #pragma unroll 2
        for (int i = 0; i < 16; i++) {
            int tl = i * 4;
            do_strip<true>(xc, tl, q, w, bs2, outb + tl * CC, t0 + tl, store_en);
        }
    } else {
        #pragma unroll 2
        for (int i = 0; i < 16; i++) {
            int tl = i * 4;
            do_strip<false>(xc, tl, q, w, bs2, outb + tl * CC, t0 + tl, store_en);
        }
    }
}

// ---------------------------------------------------------------------------
extern "C" void kernel_launch(void* const* d_in, const int* in_sizes, int n_in,
                              void* d_out, int out_size) {
    const float* x    = (const float*)d_in[0];   // [B, C, T]
    const float* W    = (const float*)d_in[1];   // [C, K, 6]
    const float* bias = (const float*)d_in[2];   // [C, K]
    float* out = (float*)d_out;                  // [B, T, C]

    (void)in_sizes; (void)n_in; (void)out_size;

    mean_kernel<<<BB * CC, 256>>>(x);

    const int smem_bytes = (CH * PITCH) * (int)sizeof(float);
    cudaFuncSetAttribute(ddst_main_kernel,
                         cudaFuncAttributeMaxDynamicSharedMemorySize, smem_bytes);
    ddst_main_kernel<<<BB * NTILES * 2, NTH, smem_bytes>>>(x, W, bias, out);
}

// round 9
// speedup vs baseline: 1.6000x; 1.0672x over previous
#include <cuda_runtime.h>
#include <cuda_bf16.h>

#define BB 32
#define CC 64
#define TT 2048
#define KK 16
#define NST 6

#define TILE 64
#define HALO_L 16                        // 15 causal + 1 for float4 alignment
#define ROWS 82                          // scalar fill length (16 + 64 + 2)
#define ROWV 88                          // vector fill length (22 float4)
#define PITCH 92                         // mult-of-4; 92%32=28 -> good banks
#define CH 32                            // channels per CTA
#define NTH 128                          // 32 channels x 4 K-quarters
#define NTILES (TT / TILE)               // 32
#define LOG2E 1.4426950408889634f

__device__ float g_means[BB * CC];

__device__ __forceinline__ float sqrt_approx(float x) {
    float r; asm("sqrt.approx.f32 %0, %1;" : "=f"(r) : "f"(x)); return r;
}
__device__ __forceinline__ float rcp_approx(float x) {
    float r; asm("rcp.approx.f32 %0, %1;" : "=f"(r) : "f"(x)); return r;
}
__device__ __forceinline__ float ex2_approx(float x) {
    float r; asm("ex2.approx.f32 %0, %1;" : "=f"(r) : "f"(x)); return r;
}
__device__ __forceinline__ float apply_sign(float ev, float k) {
    return __uint_as_float(__float_as_uint(ev) | (__float_as_uint(k) & 0x80000000u));
}

// ---------------------------------------------------------------------------
// Kernel 1: per-(b,c) mean over T
// ---------------------------------------------------------------------------
__global__ void mean_kernel(const float* __restrict__ x) {
    int row = blockIdx.x;
    const float* xr = x + (size_t)row * TT;
    float s = 0.f;
    for (int t = threadIdx.x; t < TT; t += blockDim.x) s += xr[t];
    __shared__ float red[8];
    #pragma unroll
    for (int o = 16; o > 0; o >>= 1) s += __shfl_down_sync(0xffffffffu, s, o);
    if ((threadIdx.x & 31) == 0) red[threadIdx.x >> 5] = s;
    __syncthreads();
    if (threadIdx.x < 8) {
        s = red[threadIdx.x];
        #pragma unroll
        for (int o = 4; o > 0; o >>= 1) s += __shfl_down_sync(0xffu, s, o);
        if (threadIdx.x == 0) g_means[row] = s * (1.0f / TT);
    }
}

// ---------------------------------------------------------------------------
// Strip of 4 items. Lane q computes stats for item m=q; width-4 shfl
// broadcasts. Lane q owns conv/gather for K-quarter [4q, 4q+4).
// vg[8] loaded as two float4 (aligned); tap (m,k) = vg[1 + m + k].
// ---------------------------------------------------------------------------
template <bool EDGE>
__device__ __forceinline__ void do_strip(
    const float* __restrict__ xc,   // xc[i] == x[b,c,t0+i] (smem, zero-pad)
    int tl, int q,
    const float* __restrict__ w,    // 20 regs: per k {w0,w2,w3,w4,w5} * LOG2E
    const float* __restrict__ bs2,  // 4 regs
    float* __restrict__ outp,       // &out[b, t0+tl, c]; stride CC
    int tg0, bool store_en)
{
    const int k0 = q * 4;

    // gather taps: vg[i] = x[t0 + tl + k0 - 16 + i]; aligned 2x float4
    float vg[8];
    {
        const float4* p = reinterpret_cast<const float4*>(xc + tl + k0 - 16);
        float4 lo = p[0], hi = p[1];
        vg[0] = lo.x; vg[1] = lo.y; vg[2] = lo.z; vg[3] = lo.w;
        vg[4] = hi.x; vg[5] = hi.y; vg[6] = hi.z; vg[7] = hi.w;
    }

    // ---- own-item stats (item m = q, t = t0 + tl + q) ----
    const int ts = tl + q;
    const float a0 = xc[ts - 2], a1 = xc[ts - 1], a2 = xc[ts],
                a3 = xc[ts + 1], a4 = xc[ts + 2];
    const float s  = ((a0 + a1) + (a2 + a3)) + a4;
    const float s2 = fmaf(a0, a0, a1 * a1)
                   + fmaf(a2, a2, fmaf(a3, a3, a4 * a4));
    const float xv  = a2;
    const float avg = s * 0.2f;
    const float sd  = sqrt_approx(fmaxf(fmaf(-avg, avg, s2 * 0.2f), 1e-6f));
    const float dd  = xv - avg;
    const float tm  = dd * dd * dd;

    float mx, mn;
    if (EDGE) {
        mx = -3.402823466e38f; mn = 3.402823466e38f;
        const int tg = tg0 + q;
        #pragma unroll
        for (int j = -2; j <= 2; j++) {
            int g = tg + j;
            if (g >= 0 && g < TT) {
                float t = xc[ts + j];
                mx = fmaxf(mx, t); mn = fminf(mn, t);
            }
        }
    } else {
        mx = fmaxf(fmaxf(fmaxf(a0, a1), fmaxf(a2, a3)), a4);
        mn = fminf(fminf(fminf(a0, a1), fminf(a2, a3)), a4);
    }

    // ---- 4 items: broadcast stats, conv + softmax-gather ----
    #pragma unroll
    for (int m = 0; m < 4; m++) {
        const float xv_m = __shfl_sync(0xffffffffu, xv, m, 4);
        const float sd_m = __shfl_sync(0xffffffffu, sd, m, 4);
        const float tm_m = __shfl_sync(0xffffffffu, tm, m, 4);
        const float mx_m = __shfl_sync(0xffffffffu, mx, m, 4);
        const float mn_m = __shfl_sync(0xffffffffu, mn, m, 4);

        float kern[4], ev[4];
        #pragma unroll
        for (int k = 0; k < 4; k++) {
            const float* wk = w + k * 5;
            float a = bs2[k];
            a = fmaf(wk[0], xv_m, a);
            a = fmaf(wk[1], sd_m, a);
            a = fmaf(wk[2], tm_m, a);
            a = fmaf(wk[3], mx_m, a);
            a = fmaf(wk[4], mn_m, a);
            kern[k] = a;
        }
        #pragma unroll
        for (int k = 0; k < 4; k++) ev[k] = ex2_approx(fabsf(kern[k]));
        #pragma unroll
        for (int k = 0; k < 4; k++)
            kern[k] = vg[1 + m + k] * apply_sign(ev[k], kern[k]);

        float sum = (ev[0] + ev[1]) + (ev[2] + ev[3]);
        float acc = (kern[0] + kern[1]) + (kern[2] + kern[3]);
        sum += __shfl_xor_sync(0xffffffffu, sum, 1);
        acc += __shfl_xor_sync(0xffffffffu, acc, 1);
        sum += __shfl_xor_sync(0xffffffffu, sum, 2);
        acc += __shfl_xor_sync(0xffffffffu, acc, 2);
        if (store_en) outp[m * CC] = acc * rcp_approx(sum);
    }
}

// ---------------------------------------------------------------------------
// Kernel 2: CTA = 128 threads = 32 channels x 4 K-quarters, tile of 64 t's.
// 8 CTAs/SM (regs capped at 64).
// ---------------------------------------------------------------------------
extern __shared__ float smem[];

__global__ __launch_bounds__(NTH, 8)
void ddst_main_kernel(const float* __restrict__ x,
                      const float* __restrict__ W,
                      const float* __restrict__ bias,
                      float* __restrict__ out) {
    float* xs = smem;                   // [CH][PITCH]

    const int bt   = blockIdx.x >> 1;          // b * NTILES + tile
    const int ch0  = (blockIdx.x & 1) * CH;    // channel group base
    const int b    = bt / NTILES;
    const int tile = bt % NTILES;
    const int t0   = tile * TILE;
    const int tid  = threadIdx.x;
    const int warp = tid >> 5;
    const int lane = tid & 31;

    const float* xb = x + ((size_t)b * CC + ch0) * TT;
    const bool edge = (tile == 0) || (tile == NTILES - 1);

    // x tile + halo: warp per channel row
    if (!edge) {
        // interior: gt in [t0-16, t0+72) all valid -> float4 path (aligned)
        for (int cr = warp; cr < CH; cr += NTH / 32) {
            const float4* src4 =
                reinterpret_cast<const float4*>(xb + (size_t)cr * TT + t0 - HALO_L);
            float4* dst4 = reinterpret_cast<float4*>(xs + cr * PITCH);
            if (lane < ROWV / 4) dst4[lane] = src4[lane];
        }
    } else {
        for (int cr = warp; cr < CH; cr += NTH / 32) {
            const float* src = xb + (size_t)cr * TT;
            float* dst = xs + cr * PITCH;
            for (int j = lane; j < ROWS; j += 32) {
                int gt = t0 - HALO_L + j;
                dst[j] = (gt >= 0 && gt < TT) ? src[gt] : 0.f;
            }
        }
    }
    __syncthreads();

    const int cl = tid >> 2;          // 0..31 local channel
    const int q  = tid & 3;           // quarter = stats-item index
    const int k0 = q * 4;
    const int c  = ch0 + cl;

    const float gm = g_means[b * CC + c];
    const float* Wp = W + c * (KK * NST) + k0 * NST;
    float w[20], bs2[4];
    #pragma unroll
    for (int k = 0; k < 4; k++) {
        const float* wk6 = Wp + k * NST;
        float w0 = __ldg(wk6 + 0), w1 = __ldg(wk6 + 1), w2 = __ldg(wk6 + 2);
        float w3 = __ldg(wk6 + 3), w4 = __ldg(wk6 + 4), w5 = __ldg(wk6 + 5);
        w[k*5+0] = w0 * LOG2E;
        w[k*5+1] = w2 * LOG2E;
        w[k*5+2] = w3 * LOG2E;
        w[k*5+3] = w4 * LOG2E;
        w[k*5+4] = w5 * LOG2E;
        bs2[k] = fmaf(w1, gm, __ldg(&bias[c * KK + k0 + k])) * LOG2E;
    }

    const float* xc = xs + cl * PITCH + HALO_L;
    float* outb = out + ((size_t)b * TT + t0) * CC + c;
    const bool store_en = (q == 0);

    if (edge) {
        #pragma unroll 2
        for (int i = 0; i < 16; i++) {
            int tl = i * 4;
            do_strip<true>(xc, tl, q, w, bs2, outb + tl * CC, t0 + tl, store_en);
        }
    } else {
        #pragma unroll 2
        for (int i = 0; i < 16; i++) {
            int tl = i * 4;
            do_strip<false>(xc, tl, q, w, bs2, outb + tl * CC, t0 + tl, store_en);
        }
    }
}

// ---------------------------------------------------------------------------
extern "C" void kernel_launch(void* const* d_in, const int* in_sizes, int n_in,
                              void* d_out, int out_size) {
    const float* x    = (const float*)d_in[0];   // [B, C, T]
    const float* W    = (const float*)d_in[1];   // [C, K, 6]
    const float* bias = (const float*)d_in[2];   // [C, K]
    float* out = (float*)d_out;                  // [B, T, C]

    (void)in_sizes; (void)n_in; (void)out_size;

    mean_kernel<<<BB * CC, 256>>>(x);

    const int smem_bytes = (CH * PITCH) * (int)sizeof(float);
    cudaFuncSetAttribute(ddst_main_kernel,
                         cudaFuncAttributeMaxDynamicSharedMemorySize, smem_bytes);
    ddst_main_kernel<<<BB * NTILES * 2, NTH, smem_bytes>>>(x, W, bias, out);
}

// round 10
// speedup vs baseline: 1.8417x; 1.1511x over previous
#include <cuda_runtime.h>
#include <cuda_bf16.h>

#define BB 32
#define CC 64
#define TT 2048
#define KK 16
#define NST 6

#define TILE 64
#define HALO_L 16                        // 15 causal + 1 for float4 alignment
#define ROWS 82                          // scalar fill length (16 + 64 + 2)
#define ROWV 88                          // vector fill length (22 float4)
#define PITCH 92                         // mult-of-4; 92%32=28 -> good banks
#define CH 32                            // channels per CTA
#define NTH 128                          // 32 channels x 4 K-quarters
#define NTILES (TT / TILE)               // 32
#define LOG2E 1.4426950408889634f

__device__ float g_means[BB * CC];

__device__ __forceinline__ float sqrt_approx(float x) {
    float r; asm("sqrt.approx.f32 %0, %1;" : "=f"(r) : "f"(x)); return r;
}
__device__ __forceinline__ float rcp_approx(float x) {
    float r; asm("rcp.approx.f32 %0, %1;" : "=f"(r) : "f"(x)); return r;
}
__device__ __forceinline__ float ex2_approx(float x) {
    float r; asm("ex2.approx.f32 %0, %1;" : "=f"(r) : "f"(x)); return r;
}
__device__ __forceinline__ float apply_sign(float ev, float k) {
    return __uint_as_float(__float_as_uint(ev) | (__float_as_uint(k) & 0x80000000u));
}

// ---------------------------------------------------------------------------
// Kernel 1: per-(b,c) mean over T
// ---------------------------------------------------------------------------
__global__ void mean_kernel(const float* __restrict__ x) {
    int row = blockIdx.x;
    const float* xr = x + (size_t)row * TT;
    float s = 0.f;
    for (int t = threadIdx.x; t < TT; t += blockDim.x) s += xr[t];
    __shared__ float red[8];
    #pragma unroll
    for (int o = 16; o > 0; o >>= 1) s += __shfl_down_sync(0xffffffffu, s, o);
    if ((threadIdx.x & 31) == 0) red[threadIdx.x >> 5] = s;
    __syncthreads();
    if (threadIdx.x < 8) {
        s = red[threadIdx.x];
        #pragma unroll
        for (int o = 4; o > 0; o >>= 1) s += __shfl_down_sync(0xffu, s, o);
        if (threadIdx.x == 0) g_means[row] = s * (1.0f / TT);
    }
}

// ---------------------------------------------------------------------------
// Strip of 4 items. Lane q: stats for item m=q (width-4 shfl broadcast),
// conv/gather for K-quarter [4q, 4q+4) of ALL items, partials accumulated
// in sp/ap, then a SEL-steered reduce-scatter leaves lane q with item q's
// totals; lane q alone does rcp + store (no predicated redundancy).
// ---------------------------------------------------------------------------
template <bool EDGE>
__device__ __forceinline__ void do_strip(
    const float* __restrict__ xc,   // xc[i] == x[b,c,t0+i] (smem, zero-pad)
    int tl, int q,
    const float* __restrict__ w,    // 20 regs: per k {w0,w2,w3,w4,w5} * LOG2E
    const float* __restrict__ bs2,  // 4 regs
    float* __restrict__ outp,       // &out[b, t0+tl, c]; stride CC
    int tg0)
{
    const int k0 = q * 4;

    // gather taps: vg[i] = x[t0 + tl + k0 - 16 + i]; aligned 2x float4
    float vg[8];
    {
        const float4* p = reinterpret_cast<const float4*>(xc + tl + k0 - 16);
        float4 lo = p[0], hi = p[1];
        vg[0] = lo.x; vg[1] = lo.y; vg[2] = lo.z; vg[3] = lo.w;
        vg[4] = hi.x; vg[5] = hi.y; vg[6] = hi.z; vg[7] = hi.w;
    }

    // ---- own-item stats (item m = q, t = t0 + tl + q) ----
    const int ts = tl + q;
    const float a0 = xc[ts - 2], a1 = xc[ts - 1], a2 = xc[ts],
                a3 = xc[ts + 1], a4 = xc[ts + 2];
    const float s  = ((a0 + a1) + (a2 + a3)) + a4;
    const float s2 = fmaf(a0, a0, a1 * a1)
                   + fmaf(a2, a2, fmaf(a3, a3, a4 * a4));
    const float xv  = a2;
    const float avg = s * 0.2f;
    const float sd  = sqrt_approx(fmaxf(fmaf(-avg, avg, s2 * 0.2f), 1e-6f));
    const float dd  = xv - avg;
    const float tm  = dd * dd * dd;

    float mx, mn;
    if (EDGE) {
        mx = -3.402823466e38f; mn = 3.402823466e38f;
        const int tg = tg0 + q;
        #pragma unroll
        for (int j = -2; j <= 2; j++) {
            int g = tg + j;
            if (g >= 0 && g < TT) {
                float t = xc[ts + j];
                mx = fmaxf(mx, t); mn = fminf(mn, t);
            }
        }
    } else {
        mx = fmaxf(fmaxf(fmaxf(a0, a1), fmaxf(a2, a3)), a4);
        mn = fminf(fminf(fminf(a0, a1), fminf(a2, a3)), a4);
    }

    // ---- 4 items: broadcast stats, conv + exp + partial sums ----
    float sp[4], ap[4];
    #pragma unroll
    for (int m = 0; m < 4; m++) {
        const float xv_m = __shfl_sync(0xffffffffu, xv, m, 4);
        const float sd_m = __shfl_sync(0xffffffffu, sd, m, 4);
        const float tm_m = __shfl_sync(0xffffffffu, tm, m, 4);
        const float mx_m = __shfl_sync(0xffffffffu, mx, m, 4);
        const float mn_m = __shfl_sync(0xffffffffu, mn, m, 4);

        float kern[4], ev[4];
        #pragma unroll
        for (int k = 0; k < 4; k++) {
            const float* wk = w + k * 5;
            float a = bs2[k];
            a = fmaf(wk[0], xv_m, a);
            a = fmaf(wk[1], sd_m, a);
            a = fmaf(wk[2], tm_m, a);
            a = fmaf(wk[3], mx_m, a);
            a = fmaf(wk[4], mn_m, a);
            kern[k] = a;
        }
        #pragma unroll
        for (int k = 0; k < 4; k++) ev[k] = ex2_approx(fabsf(kern[k]));
        #pragma unroll
        for (int k = 0; k < 4; k++)
            kern[k] = vg[1 + m + k] * apply_sign(ev[k], kern[k]);

        sp[m] = (ev[0] + ev[1]) + (ev[2] + ev[3]);
        ap[m] = (kern[0] + kern[1]) + (kern[2] + kern[3]);
    }

    // ---- reduce-scatter over the 4-lane group: lane q ends with item q ----
    const bool hi2 = (q & 2) != 0;
    const bool hi1 = (q & 1) != 0;

    // step 1 (distance 2): halves exchange the two chunks the other half owns
    float sk0 = hi2 ? sp[2] : sp[0];
    float sk1 = hi2 ? sp[3] : sp[1];
    float ss0 = hi2 ? sp[0] : sp[2];
    float ss1 = hi2 ? sp[1] : sp[3];
    float ak0 = hi2 ? ap[2] : ap[0];
    float ak1 = hi2 ? ap[3] : ap[1];
    float as0 = hi2 ? ap[0] : ap[2];
    float as1 = hi2 ? ap[1] : ap[3];
    sk0 += __shfl_xor_sync(0xffffffffu, ss0, 2);
    sk1 += __shfl_xor_sync(0xffffffffu, ss1, 2);
    ak0 += __shfl_xor_sync(0xffffffffu, as0, 2);
    ak1 += __shfl_xor_sync(0xffffffffu, as1, 2);

    // step 2 (distance 1): pair exchanges the remaining non-owned chunk
    float skeep = hi1 ? sk1 : sk0;
    float ssend = hi1 ? sk0 : sk1;
    float akeep = hi1 ? ak1 : ak0;
    float asend = hi1 ? ak0 : ak1;
    float S = skeep + __shfl_xor_sync(0xffffffffu, ssend, 1);
    float A = akeep + __shfl_xor_sync(0xffffffffu, asend, 1);

    // lane q stores item q (warp stores 32 distinct (t,c) -> 1 STG)
    outp[q * CC] = A * rcp_approx(S);
}

// ---------------------------------------------------------------------------
// Kernel 2: CTA = 128 threads = 32 channels x 4 K-quarters, tile of 64 t's.
// 8 CTAs/SM (regs capped at 64).
// ---------------------------------------------------------------------------
extern __shared__ float smem[];

__global__ __launch_bounds__(NTH, 8)
void ddst_main_kernel(const float* __restrict__ x,
                      const float* __restrict__ W,
                      const float* __restrict__ bias,
                      float* __restrict__ out) {
    float* xs = smem;                   // [CH][PITCH]

    const int bt   = blockIdx.x >> 1;          // b * NTILES + tile
    const int ch0  = (blockIdx.x & 1) * CH;    // channel group base
    const int b    = bt / NTILES;
    const int tile = bt % NTILES;
    const int t0   = tile * TILE;
    const int tid  = threadIdx.x;

    const float* xb = x + ((size_t)b * CC + ch0) * TT;
    const bool edge = (tile == 0) || (tile == NTILES - 1);

    // x tile + halo
    if (!edge) {
        // interior: all gt valid -> float4 path, all 128 lanes useful
        const int NV = ROWV / 4;               // 22 float4 per row
        for (int idx = tid; idx < CH * NV; idx += NTH) {
            int cr = idx / NV;
            int j  = idx - cr * NV;
            const float4* src4 =
                reinterpret_cast<const float4*>(xb + (size_t)cr * TT + t0 - HALO_L);
            reinterpret_cast<float4*>(xs + cr * PITCH)[j] = src4[j];
        }
    } else {
        const int warp = tid >> 5;
        const int lane = tid & 31;
        for (int cr = warp; cr < CH; cr += NTH / 32) {
            const float* src = xb + (size_t)cr * TT;
            float* dst = xs + cr * PITCH;
            for (int j = lane; j < ROWS; j += 32) {
                int gt = t0 - HALO_L + j;
                dst[j] = (gt >= 0 && gt < TT) ? src[gt] : 0.f;
            }
        }
    }
    __syncthreads();

    const int cl = tid >> 2;          // 0..31 local channel
    const int q  = tid & 3;           // quarter = stats-item = store-item
    const int k0 = q * 4;
    const int c  = ch0 + cl;

    const float gm = g_means[b * CC + c];
    const float* Wp = W + c * (KK * NST) + k0 * NST;
    float w[20], bs2[4];
    #pragma unroll
    for (int k = 0; k < 4; k++) {
        const float* wk6 = Wp + k * NST;
        float w0 = __ldg(wk6 + 0), w1 = __ldg(wk6 + 1), w2 = __ldg(wk6 + 2);
        float w3 = __ldg(wk6 + 3), w4 = __ldg(wk6 + 4), w5 = __ldg(wk6 + 5);
        w[k*5+0] = w0 * LOG2E;
        w[k*5+1] = w2 * LOG2E;
        w[k*5+2] = w3 * LOG2E;
        w[k*5+3] = w4 * LOG2E;
        w[k*5+4] = w5 * LOG2E;
        bs2[k] = fmaf(w1, gm, __ldg(&bias[c * KK + k0 + k])) * LOG2E;
    }

    const float* xc = xs + cl * PITCH + HALO_L;
    float* outb = out + ((size_t)b * TT + t0) * CC + c;

    if (edge) {
        #pragma unroll 2
        for (int i = 0; i < 16; i++) {
            int tl = i * 4;
            do_strip<true>(xc, tl, q, w, bs2, outb + tl * CC, t0 + tl);
        }
    } else {
        #pragma unroll 2
        for (int i = 0; i < 16; i++) {
            int tl = i * 4;
            do_strip<false>(xc, tl, q, w, bs2, outb + tl * CC, t0 + tl);
        }
    }
}

// ---------------------------------------------------------------------------
extern "C" void kernel_launch(void* const* d_in, const int* in_sizes, int n_in,
                              void* d_out, int out_size) {
    const float* x    = (const float*)d_in[0];   // [B, C, T]
    const float* W    = (const float*)d_in[1];   // [C, K, 6]
    const float* bias = (const float*)d_in[2];   // [C, K]
    float* out = (float*)d_out;                  // [B, T, C]

    (void)in_sizes; (void)n_in; (void)out_size;

    mean_kernel<<<BB * CC, 256>>>(x);

    const int smem_bytes = (CH * PITCH) * (int)sizeof(float);
    cudaFuncSetAttribute(ddst_main_kernel,
                         cudaFuncAttributeMaxDynamicSharedMemorySize, smem_bytes);
    ddst_main_kernel<<<BB * NTILES * 2, NTH, smem_bytes>>>(x, W, bias, out);
}

// round 11
// speedup vs baseline: 1.9188x; 1.0418x over previous
#include <cuda_runtime.h>
#include <cuda_bf16.h>

#define BB 32
#define CC 64
#define TT 2048
#define KK 16
#define NST 6

#define TILE 128                         // t-range per CTA
#define HALO_L 16                        // 15 causal + 1 for float4 alignment
#define ROWS 146                         // scalar fill (16 + 128 + 2)
#define ROWV 152                         // vector fill (38 float4)
#define PITCH 156                        // mult-4; (156*cl)%32 = 28cl -> distinct banks
#define CH 32                            // channels per CTA
#define NTH 128                          // 32 channels x 4 K-quarters
#define NTILES (TT / TILE)               // 16
#define LOG2E 1.4426950408889634f

__device__ float g_means[BB * CC];

__device__ __forceinline__ float sqrt_approx(float x) {
    float r; asm("sqrt.approx.f32 %0, %1;" : "=f"(r) : "f"(x)); return r;
}
__device__ __forceinline__ float rcp_approx(float x) {
    float r; asm("rcp.approx.f32 %0, %1;" : "=f"(r) : "f"(x)); return r;
}
__device__ __forceinline__ float ex2_approx(float x) {
    float r; asm("ex2.approx.f32 %0, %1;" : "=f"(r) : "f"(x)); return r;
}
__device__ __forceinline__ float apply_sign(float ev, float k) {
    return __uint_as_float(__float_as_uint(ev) | (__float_as_uint(k) & 0x80000000u));
}

// ---------------------------------------------------------------------------
// Kernel 1: per-(b,c) mean over T
// ---------------------------------------------------------------------------
__global__ void mean_kernel(const float* __restrict__ x) {
    int row = blockIdx.x;
    const float* xr = x + (size_t)row * TT;
    float s = 0.f;
    for (int t = threadIdx.x; t < TT; t += blockDim.x) s += xr[t];
    __shared__ float red[8];
    #pragma unroll
    for (int o = 16; o > 0; o >>= 1) s += __shfl_down_sync(0xffffffffu, s, o);
    if ((threadIdx.x & 31) == 0) red[threadIdx.x >> 5] = s;
    __syncthreads();
    if (threadIdx.x < 8) {
        s = red[threadIdx.x];
        #pragma unroll
        for (int o = 4; o > 0; o >>= 1) s += __shfl_down_sync(0xffu, s, o);
        if (threadIdx.x == 0) g_means[row] = s * (1.0f / TT);
    }
}

// ---------------------------------------------------------------------------
// Strip of 4 items. Lane q: stats for item m=q (4 shfl broadcasts; xv comes
// from one aligned LDS.128 instead of a 5th broadcast), conv/gather for
// K-quarter [4q,4q+4), SEL-steered reduce-scatter -> lane q stores item q.
// ---------------------------------------------------------------------------
template <bool EDGE>
__device__ __forceinline__ void do_strip(
    const float* __restrict__ xc,   // xc[i] == x[b,c,t0+i] (smem, zero-pad)
    int tl, int q,
    const float* __restrict__ w,    // 20 regs: per k {w0,w2,w3,w4,w5} * LOG2E
    const float* __restrict__ bs2,  // 4 regs
    float* __restrict__ outp,       // &out[b, t0+tl, c]; stride CC
    int tg0)
{
    const int k0 = q * 4;

    // gather taps: vg[i] = x[t0 + tl + k0 - 16 + i]; aligned 2x float4
    float vg[8];
    {
        const float4* p = reinterpret_cast<const float4*>(xc + tl + k0 - 16);
        float4 lo = p[0], hi = p[1];
        vg[0] = lo.x; vg[1] = lo.y; vg[2] = lo.z; vg[3] = lo.w;
        vg[4] = hi.x; vg[5] = hi.y; vg[6] = hi.z; vg[7] = hi.w;
    }
    // center values of the 4 items (one aligned LDS.128, replaces 4 SHFLs)
    const float4 xq = *reinterpret_cast<const float4*>(xc + tl);

    // ---- own-item stats (item m = q, t = t0 + tl + q) ----
    const int ts = tl + q;
    const float a0 = xc[ts - 2], a1 = xc[ts - 1], a2 = xc[ts],
                a3 = xc[ts + 1], a4 = xc[ts + 2];
    const float s  = ((a0 + a1) + (a2 + a3)) + a4;
    const float s2 = fmaf(a0, a0, a1 * a1)
                   + fmaf(a2, a2, fmaf(a3, a3, a4 * a4));
    const float avg = s * 0.2f;
    const float sd  = sqrt_approx(fmaxf(fmaf(-avg, avg, s2 * 0.2f), 1e-6f));
    const float dd  = a2 - avg;
    const float tm  = dd * dd * dd;

    float mx, mn;
    if (EDGE) {
        mx = -3.402823466e38f; mn = 3.402823466e38f;
        const int tg = tg0 + q;
        #pragma unroll
        for (int j = -2; j <= 2; j++) {
            int g = tg + j;
            if (g >= 0 && g < TT) {
                float t = xc[ts + j];
                mx = fmaxf(mx, t); mn = fminf(mn, t);
            }
        }
    } else {
        mx = fmaxf(fmaxf(fmaxf(a0, a1), fmaxf(a2, a3)), a4);
        mn = fminf(fminf(fminf(a0, a1), fminf(a2, a3)), a4);
    }

    // ---- 4 items: broadcast 4 stats each, conv + exp + partial sums ----
    float sp[4], ap[4];
    #pragma unroll
    for (int m = 0; m < 4; m++) {
        const float xv_m = (m == 0) ? xq.x : (m == 1) ? xq.y
                         : (m == 2) ? xq.z : xq.w;
        const float sd_m = __shfl_sync(0xffffffffu, sd, m, 4);
        const float tm_m = __shfl_sync(0xffffffffu, tm, m, 4);
        const float mx_m = __shfl_sync(0xffffffffu, mx, m, 4);
        const float mn_m = __shfl_sync(0xffffffffu, mn, m, 4);

        float kern[4], ev[4];
        #pragma unroll
        for (int k = 0; k < 4; k++) {
            const float* wk = w + k * 5;
            float a = bs2[k];
            a = fmaf(wk[0], xv_m, a);
            a = fmaf(wk[1], sd_m, a);
            a = fmaf(wk[2], tm_m, a);
            a = fmaf(wk[3], mx_m, a);
            a = fmaf(wk[4], mn_m, a);
            kern[k] = a;
        }
        #pragma unroll
        for (int k = 0; k < 4; k++) ev[k] = ex2_approx(fabsf(kern[k]));
        #pragma unroll
        for (int k = 0; k < 4; k++)
            kern[k] = vg[1 + m + k] * apply_sign(ev[k], kern[k]);

        sp[m] = (ev[0] + ev[1]) + (ev[2] + ev[3]);
        ap[m] = (kern[0] + kern[1]) + (kern[2] + kern[3]);
    }

    // ---- reduce-scatter over the 4-lane group: lane q ends with item q ----
    const bool hi2 = (q & 2) != 0;
    const bool hi1 = (q & 1) != 0;

    float sk0 = hi2 ? sp[2] : sp[0];
    float sk1 = hi2 ? sp[3] : sp[1];
    float ss0 = hi2 ? sp[0] : sp[2];
    float ss1 = hi2 ? sp[1] : sp[3];
    float ak0 = hi2 ? ap[2] : ap[0];
    float ak1 = hi2 ? ap[3] : ap[1];
    float as0 = hi2 ? ap[0] : ap[2];
    float as1 = hi2 ? ap[1] : ap[3];
    sk0 += __shfl_xor_sync(0xffffffffu, ss0, 2);
    sk1 += __shfl_xor_sync(0xffffffffu, ss1, 2);
    ak0 += __shfl_xor_sync(0xffffffffu, as0, 2);
    ak1 += __shfl_xor_sync(0xffffffffu, as1, 2);

    float skeep = hi1 ? sk1 : sk0;
    float ssend = hi1 ? sk0 : sk1;
    float akeep = hi1 ? ak1 : ak0;
    float asend = hi1 ? ak0 : ak1;
    float S = skeep + __shfl_xor_sync(0xffffffffu, ssend, 1);
    float A = akeep + __shfl_xor_sync(0xffffffffu, asend, 1);

    outp[q * CC] = A * rcp_approx(S);
}

// ---------------------------------------------------------------------------
// Kernel 2: CTA = 128 threads = 32 channels x 4 K-quarters, 128 t's per CTA
// (32 strips -> prologue/barrier amortized 2x). 8 CTAs/SM.
// ---------------------------------------------------------------------------
extern __shared__ float smem[];

__global__ __launch_bounds__(NTH, 8)
void ddst_main_kernel(const float* __restrict__ x,
                      const float* __restrict__ W,
                      const float* __restrict__ bias,
                      float* __restrict__ out) {
    float* xs = smem;                   // [CH][PITCH]

    const int bt   = blockIdx.x >> 1;          // b * NTILES + tile
    const int ch0  = (blockIdx.x & 1) * CH;    // channel group base
    const int b    = bt / NTILES;
    const int tile = bt % NTILES;
    const int t0   = tile * TILE;
    const int tid  = threadIdx.x;

    const float* xb = x + ((size_t)b * CC + ch0) * TT;
    const bool edge = (tile == 0) || (tile == NTILES - 1);

    // x tile + halo
    if (!edge) {
        const int NV = ROWV / 4;               // 38 float4 per row
        for (int idx = tid; idx < CH * NV; idx += NTH) {
            int cr = idx / NV;
            int j  = idx - cr * NV;
            const float4* src4 =
                reinterpret_cast<const float4*>(xb + (size_t)cr * TT + t0 - HALO_L);
            reinterpret_cast<float4*>(xs + cr * PITCH)[j] = src4[j];
        }
    } else {
        const int warp = tid >> 5;
        const int lane = tid & 31;
        for (int cr = warp; cr < CH; cr += NTH / 32) {
            const float* src = xb + (size_t)cr * TT;
            float* dst = xs + cr * PITCH;
            for (int j = lane; j < ROWS; j += 32) {
                int gt = t0 - HALO_L + j;
                dst[j] = (gt >= 0 && gt < TT) ? src[gt] : 0.f;
            }
        }
    }
    __syncthreads();

    const int cl = tid >> 2;          // 0..31 local channel
    const int q  = tid & 3;           // quarter = stats-item = store-item
    const int k0 = q * 4;
    const int c  = ch0 + cl;

    const float gm = g_means[b * CC + c];
    const float* Wp = W + c * (KK * NST) + k0 * NST;
    float w[20], bs2[4];
    #pragma unroll
    for (int k = 0; k < 4; k++) {
        const float* wk6 = Wp + k * NST;
        float w0 = __ldg(wk6 + 0), w1 = __ldg(wk6 + 1), w2 = __ldg(wk6 + 2);
        float w3 = __ldg(wk6 + 3), w4 = __ldg(wk6 + 4), w5 = __ldg(wk6 + 5);
        w[k*5+0] = w0 * LOG2E;
        w[k*5+1] = w2 * LOG2E;
        w[k*5+2] = w3 * LOG2E;
        w[k*5+3] = w4 * LOG2E;
        w[k*5+4] = w5 * LOG2E;
        bs2[k] = fmaf(w1, gm, __ldg(&bias[c * KK + k0 + k])) * LOG2E;
    }

    const float* xc = xs + cl * PITCH + HALO_L;
    float* outb = out + ((size_t)b * TT + t0) * CC + c;

    if (edge) {
        #pragma unroll 2
        for (int i = 0; i < TILE / 4; i++) {
            int tl = i * 4;
            do_strip<true>(xc, tl, q, w, bs2, outb + tl * CC, t0 + tl);
        }
    } else {
        #pragma unroll 2
        for (int i = 0; i < TILE / 4; i++) {
            int tl = i * 4;
            do_strip<false>(xc, tl, q, w, bs2, outb + tl * CC, t0 + tl);
        }
    }
}

// ---------------------------------------------------------------------------
extern "C" void kernel_launch(void* const* d_in, const int* in_sizes, int n_in,
                              void* d_out, int out_size) {
    const float* x    = (const float*)d_in[0];   // [B, C, T]
    const float* W    = (const float*)d_in[1];   // [C, K, 6]
    const float* bias = (const float*)d_in[2];   // [C, K]
    float* out = (float*)d_out;                  // [B, T, C]

    (void)in_sizes; (void)n_in; (void)out_size;

    mean_kernel<<<BB * CC, 256>>>(x);

    const int smem_bytes = (CH * PITCH) * (int)sizeof(float);
    cudaFuncSetAttribute(ddst_main_kernel,
                         cudaFuncAttributeMaxDynamicSharedMemorySize, smem_bytes);
    ddst_main_kernel<<<BB * NTILES * 2, NTH, smem_bytes>>>(x, W, bias, out);
}